// round 1
// baseline (speedup 1.0000x reference)
#include <cuda_runtime.h>
#include <cstdint>

#define T_STEPS 128
#define BATCH   64
#define VDIM    2048
#define HDIM    1024
#define GDIM    4096   // 4*H

// ---------------- scratch (static device globals; no allocation) ----------
__device__ float g_gates[(size_t)T_STEPS * BATCH * GDIM];  // 134 MB: x@Wi + b
__device__ float g_h[2][BATCH * HDIM];
__device__ float g_c[2][BATCH * HDIM];
__device__ int   g_eos[2][BATCH];

// ---------------- helpers ------------------------------------------------
__device__ __forceinline__ uint32_t f2tf32(float f) {
    uint32_t r;
    asm("cvt.rna.tf32.f32 %0, %1;" : "=r"(r) : "f"(f));
    return r;
}

__device__ __forceinline__ void mma_tf32(float c[4],
                                         uint32_t a0, uint32_t a1, uint32_t a2, uint32_t a3,
                                         uint32_t b0, uint32_t b1) {
    asm volatile(
        "mma.sync.aligned.m16n8k8.row.col.f32.tf32.tf32.f32 "
        "{%0,%1,%2,%3}, {%4,%5,%6,%7}, {%8,%9}, {%0,%1,%2,%3};\n"
        : "+f"(c[0]), "+f"(c[1]), "+f"(c[2]), "+f"(c[3])
        : "r"(a0), "r"(a1), "r"(a2), "r"(a3), "r"(b0), "r"(b1));
}

__device__ __forceinline__ float sigf(float x) {
    return 1.0f / (1.0f + expf(-x));
}

// ---------------- init state ---------------------------------------------
__global__ void init_state(const float* __restrict__ c0,
                           const float* __restrict__ h0,
                           const unsigned char* __restrict__ eos0) {
    int i = blockIdx.x * blockDim.x + threadIdx.x;
    if (i < BATCH * HDIM) {
        g_c[0][i] = c0[i];
        g_h[0][i] = h0[i];
    }
    if (i < BATCH) g_eos[0][i] = eos0[i] ? 1 : 0;
}

// ---------------- phase 1: gates_x = X @ Wi + b  (tf32 mma) ---------------
// M = T*B = 8192, N = 4096, K = 2048.  CTA tile 128x128, BK=16.
#define G1_BM 128
#define G1_BN 128
#define G1_BK 16
#define G1_ASTR 20    // padded row stride for As (16B aligned, shifts banks)
#define G1_BSTR 132   // padded row stride for Bs

__global__ __launch_bounds__(256) void gemm1(const float* __restrict__ X,
                                             const float* __restrict__ Wi,
                                             const float* __restrict__ bias) {
    __shared__ float As[G1_BM * G1_ASTR];
    __shared__ float Bs[G1_BK * G1_BSTR];

    const int tid  = threadIdx.x;
    const int lane = tid & 31;
    const int wid  = tid >> 5;            // 8 warps: 4 (M) x 2 (N)
    const int wm   = (wid >> 1) * 32;     // warp M offset within CTA tile
    const int wn   = (wid & 1) * 64;      // warp N offset within CTA tile
    const int lq   = lane >> 2;           // 0..7
    const int lr   = lane & 3;            // 0..3

    const int m0 = blockIdx.y * G1_BM;
    const int n0 = blockIdx.x * G1_BN;

    float acc[2][8][4];
#pragma unroll
    for (int mi = 0; mi < 2; mi++)
#pragma unroll
        for (int ni = 0; ni < 8; ni++)
#pragma unroll
            for (int q = 0; q < 4; q++) acc[mi][ni][q] = 0.0f;

    const int ar = tid >> 1;              // 0..127 (A row)
    const int ac = (tid & 1) * 8;         // 0 or 8  (A k-col)
    const int br = tid >> 4;              // 0..15   (B k-row)
    const int bc = (tid & 15) * 8;        // 0..120  (B n-col)

    for (int k0 = 0; k0 < VDIM; k0 += G1_BK) {
        // load A tile 128x16
        const float4* ag = (const float4*)(X + (size_t)(m0 + ar) * VDIM + k0 + ac);
        float4 av0 = ag[0], av1 = ag[1];
        *(float4*)(As + ar * G1_ASTR + ac)     = av0;
        *(float4*)(As + ar * G1_ASTR + ac + 4) = av1;
        // load B tile 16x128
        const float4* bg = (const float4*)(Wi + (size_t)(k0 + br) * GDIM + n0 + bc);
        float4 bv0 = bg[0], bv1 = bg[1];
        *(float4*)(Bs + br * G1_BSTR + bc)     = bv0;
        *(float4*)(Bs + br * G1_BSTR + bc + 4) = bv1;
        __syncthreads();

#pragma unroll
        for (int kk = 0; kk < G1_BK; kk += 8) {
            uint32_t afr[2][4];
#pragma unroll
            for (int mi = 0; mi < 2; mi++) {
                int r = wm + mi * 16 + lq;
                afr[mi][0] = f2tf32(As[r * G1_ASTR + kk + lr]);
                afr[mi][1] = f2tf32(As[(r + 8) * G1_ASTR + kk + lr]);
                afr[mi][2] = f2tf32(As[r * G1_ASTR + kk + lr + 4]);
                afr[mi][3] = f2tf32(As[(r + 8) * G1_ASTR + kk + lr + 4]);
            }
            uint32_t bfr[8][2];
#pragma unroll
            for (int ni = 0; ni < 8; ni++) {
                int c = wn + ni * 8 + lq;
                bfr[ni][0] = f2tf32(Bs[(kk + lr) * G1_BSTR + c]);
                bfr[ni][1] = f2tf32(Bs[(kk + lr + 4) * G1_BSTR + c]);
            }
#pragma unroll
            for (int mi = 0; mi < 2; mi++)
#pragma unroll
                for (int ni = 0; ni < 8; ni++)
                    mma_tf32(acc[mi][ni], afr[mi][0], afr[mi][1], afr[mi][2], afr[mi][3],
                             bfr[ni][0], bfr[ni][1]);
        }
        __syncthreads();
    }

    // epilogue: write gates_x = acc + bias
#pragma unroll
    for (int mi = 0; mi < 2; mi++) {
#pragma unroll
        for (int ni = 0; ni < 8; ni++) {
            int r0 = m0 + wm + mi * 16 + lq;
            int c0 = n0 + wn + ni * 8 + 2 * lr;
            float bl = bias[c0];
            float bh = bias[c0 + 1];
            g_gates[(size_t)r0 * GDIM + c0]             = acc[mi][ni][0] + bl;
            g_gates[(size_t)r0 * GDIM + c0 + 1]         = acc[mi][ni][1] + bh;
            g_gates[(size_t)(r0 + 8) * GDIM + c0]       = acc[mi][ni][2] + bl;
            g_gates[(size_t)(r0 + 8) * GDIM + c0 + 1]   = acc[mi][ni][3] + bh;
        }
    }
}

// ---------------- phase 2: one fused kernel per timestep -------------------
// CTA j (0..127) owns hidden units [j*8, j*8+8) and computes all 4 gates for
// them:  gates = gates_x[t] + h_prev @ Wh  ->  LSTM cell -> ys[t], c/h next.
// 128 threads = 4 warps; warp w handles batch rows [w*16, w*16+16).
#define HS_STR 36
#define WS_STR 36

__global__ __launch_bounds__(128) void lstm_step(const float* __restrict__ X,
                                                 const float* __restrict__ Wh,
                                                 float* __restrict__ ys,
                                                 int t) {
    __shared__ float hs[64 * HS_STR];   // h tile: 64 rows x 32 k
    __shared__ float ws[32 * WS_STR];   // Wh tile: 32 k x 32 cols (4 gates x 8)

    const int tid  = threadIdx.x;
    const int lane = tid & 31;
    const int w    = tid >> 5;         // warp 0..3
    const int lq   = lane >> 2;        // 0..7
    const int lr   = lane & 3;         // 0..3
    const int j    = blockIdx.x;       // hidden slice

    const int cur = t & 1;
    const int nxt = (t + 1) & 1;
    const float* __restrict__ hprev = g_h[cur];

    float acc[4][4];
#pragma unroll
    for (int g = 0; g < 4; g++)
#pragma unroll
        for (int q = 0; q < 4; q++) acc[g][q] = 0.0f;

    const int hr = tid >> 1;           // 0..63
    const int hc = (tid & 1) * 16;     // 0 or 16
    const int wk = tid >> 2;           // 0..31
    const int wg = tid & 3;            // gate 0..3

    for (int k0 = 0; k0 < HDIM; k0 += 32) {
        // h tile: 64x32
#pragma unroll
        for (int v = 0; v < 4; v++)
            *(float4*)(hs + hr * HS_STR + hc + v * 4) =
                *(const float4*)(hprev + hr * HDIM + k0 + hc + v * 4);
        // Wh tile: rows k0+wk, cols for gate wg: wg*1024 + j*8 .. +8
        const float4* wsrc = (const float4*)(Wh + (size_t)(k0 + wk) * GDIM + wg * HDIM + j * 8);
        *(float4*)(ws + wk * WS_STR + wg * 8)     = wsrc[0];
        *(float4*)(ws + wk * WS_STR + wg * 8 + 4) = wsrc[1];
        __syncthreads();

#pragma unroll
        for (int kk = 0; kk < 32; kk += 8) {
            int r = w * 16 + lq;
            uint32_t a0 = f2tf32(hs[r * HS_STR + kk + lr]);
            uint32_t a1 = f2tf32(hs[(r + 8) * HS_STR + kk + lr]);
            uint32_t a2 = f2tf32(hs[r * HS_STR + kk + lr + 4]);
            uint32_t a3 = f2tf32(hs[(r + 8) * HS_STR + kk + lr + 4]);
#pragma unroll
            for (int g = 0; g < 4; g++) {
                uint32_t b0 = f2tf32(ws[(kk + lr) * WS_STR + g * 8 + lq]);
                uint32_t b1 = f2tf32(ws[(kk + lr + 4) * WS_STR + g * 8 + lq]);
                mma_tf32(acc[g], a0, a1, a2, a3, b0, b1);
            }
        }
        __syncthreads();
    }

    // ---- elementwise LSTM cell (bias already folded into g_gates) ----
    const float* __restrict__ gx    = g_gates + (size_t)t * BATCH * GDIM;
    const float* __restrict__ cprev = g_c[cur];
    float* __restrict__ cnex = g_c[nxt];
    float* __restrict__ hnex = g_h[nxt];
    const int* __restrict__ eosc = g_eos[cur];

#pragma unroll
    for (int half = 0; half < 2; half++) {
        int r = w * 16 + lq + half * 8;   // batch row
        bool m = (eosc[r] != 0);
#pragma unroll
        for (int cc = 0; cc < 2; cc++) {
            int ci   = half * 2 + cc;
            int hcol = j * 8 + 2 * lr + cc;
            float iv = acc[0][ci] + gx[(size_t)r * GDIM + hcol];
            float fv = acc[1][ci] + gx[(size_t)r * GDIM + HDIM + hcol];
            float gv = acc[2][ci] + gx[(size_t)r * GDIM + 2 * HDIM + hcol];
            float ov = acc[3][ci] + gx[(size_t)r * GDIM + 3 * HDIM + hcol];

            float cp  = cprev[r * HDIM + hcol];
            float ncv = sigf(fv) * cp + sigf(iv) * tanhf(gv);
            float nhv = sigf(ov) * tanhf(ncv);

            ys[((size_t)t * BATCH + r) * HDIM + hcol] = nhv;            // unmasked
            cnex[r * HDIM + hcol] = m ? cp : ncv;
            hnex[r * HDIM + hcol] = m ? hprev[r * HDIM + hcol] : nhv;
        }
    }

    // eos_next = eos_prev | (x[t, b, EOS_ID] != 0); written to next buffer
    if (blockIdx.x == 0 && tid < BATCH) {
        float xe = X[((size_t)t * BATCH + tid) * VDIM + 1];
        g_eos[nxt][tid] = (eosc[tid] != 0 || xe != 0.0f) ? 1 : 0;
    }
}

// ---------------- launch ---------------------------------------------------
extern "C" void kernel_launch(void* const* d_in, const int* in_sizes, int n_in,
                              void* d_out, int out_size) {
    const float* x  = (const float*)d_in[0];
    const float* Wi = (const float*)d_in[1];
    const float* Wh = (const float*)d_in[2];
    const float* b  = (const float*)d_in[3];
    const float* c0 = (const float*)d_in[4];
    const float* h0 = (const float*)d_in[5];
    const unsigned char* eos0 = (const unsigned char*)d_in[6];
    float* ys = (float*)d_out;

    init_state<<<(BATCH * HDIM + 255) / 256, 256>>>(c0, h0, eos0);

    dim3 g1(GDIM / G1_BN, (T_STEPS * BATCH) / G1_BM);   // 32 x 64
    gemm1<<<g1, 256>>>(x, Wi, b);

    for (int t = 0; t < T_STEPS; t++)
        lstm_step<<<128, 128>>>(x, Wh, ys, t);
}

// round 3
// speedup vs baseline: 1.7872x; 1.7872x over previous
#include <cuda_runtime.h>
#include <cstdint>

#define T_STEPS 128
#define BATCH   64
#define VDIM    2048
#define HDIM    1024
#define GDIM    4096   // 4*H

#define NCTA    128    // persistent CTAs (one per 8 hidden units)
#define NTHR    128    // 4 warps (round-1 layout)

// ---------------- scratch (static device globals; no allocation) ----------
__device__ float g_gates[(size_t)T_STEPS * BATCH * GDIM];  // 134 MB: x@Wi + b
__device__ float g_h[2][BATCH * HDIM];
__device__ float g_c[2][BATCH * HDIM];
__device__ int   g_eos[2][BATCH];
__device__ unsigned g_bar_count;
__device__ volatile unsigned g_bar_gen;

// ---------------- helpers ------------------------------------------------
__device__ __forceinline__ uint32_t f2tf32(float f) {
    uint32_t r;
    asm("cvt.rna.tf32.f32 %0, %1;" : "=r"(r) : "f"(f));
    return r;
}

__device__ __forceinline__ void mma_tf32(float c[4],
                                         uint32_t a0, uint32_t a1, uint32_t a2, uint32_t a3,
                                         uint32_t b0, uint32_t b1) {
    asm volatile(
        "mma.sync.aligned.m16n8k8.row.col.f32.tf32.tf32.f32 "
        "{%0,%1,%2,%3}, {%4,%5,%6,%7}, {%8,%9}, {%0,%1,%2,%3};\n"
        : "+f"(c[0]), "+f"(c[1]), "+f"(c[2]), "+f"(c[3])
        : "r"(a0), "r"(a1), "r"(a2), "r"(a3), "r"(b0), "r"(b1));
}

__device__ __forceinline__ float sigf(float x) {
    return 1.0f / (1.0f + expf(-x));
}

__device__ __forceinline__ float4 ldcg4(const float* p) {
    return __ldcg((const float4*)p);
}

// ---------------- init state ---------------------------------------------
__global__ void init_state(const float* __restrict__ c0,
                           const float* __restrict__ h0,
                           const unsigned char* __restrict__ eos0) {
    int i = blockIdx.x * blockDim.x + threadIdx.x;
    if (i < BATCH * HDIM) {
        g_c[0][i] = c0[i];
        g_h[0][i] = h0[i];
    }
    if (i < BATCH) g_eos[0][i] = eos0[i] ? 1 : 0;
    if (i == 0) { g_bar_count = 0; g_bar_gen = 0; }
}

// ---------------- phase 1: gates_x = X @ Wi + b  (round-1 proven version) --
#define G1_BM 128
#define G1_BN 128
#define G1_BK 16
#define G1_ASTR 20
#define G1_BSTR 132

__global__ __launch_bounds__(256) void gemm1(const float* __restrict__ X,
                                             const float* __restrict__ Wi,
                                             const float* __restrict__ bias) {
    __shared__ float As[G1_BM * G1_ASTR];
    __shared__ float Bs[G1_BK * G1_BSTR];

    const int tid  = threadIdx.x;
    const int lane = tid & 31;
    const int wid  = tid >> 5;
    const int wm   = (wid >> 1) * 32;
    const int wn   = (wid & 1) * 64;
    const int lq   = lane >> 2;
    const int lr   = lane & 3;

    const int m0 = blockIdx.y * G1_BM;
    const int n0 = blockIdx.x * G1_BN;

    float acc[2][8][4];
#pragma unroll
    for (int mi = 0; mi < 2; mi++)
#pragma unroll
        for (int ni = 0; ni < 8; ni++)
#pragma unroll
            for (int q = 0; q < 4; q++) acc[mi][ni][q] = 0.0f;

    const int ar = tid >> 1;
    const int ac = (tid & 1) * 8;
    const int br = tid >> 4;
    const int bc = (tid & 15) * 8;

    for (int k0 = 0; k0 < VDIM; k0 += G1_BK) {
        const float4* ag = (const float4*)(X + (size_t)(m0 + ar) * VDIM + k0 + ac);
        float4 av0 = ag[0], av1 = ag[1];
        *(float4*)(As + ar * G1_ASTR + ac)     = av0;
        *(float4*)(As + ar * G1_ASTR + ac + 4) = av1;
        const float4* bg = (const float4*)(Wi + (size_t)(k0 + br) * GDIM + n0 + bc);
        float4 bv0 = bg[0], bv1 = bg[1];
        *(float4*)(Bs + br * G1_BSTR + bc)     = bv0;
        *(float4*)(Bs + br * G1_BSTR + bc + 4) = bv1;
        __syncthreads();

#pragma unroll
        for (int kk = 0; kk < G1_BK; kk += 8) {
            uint32_t afr[2][4];
#pragma unroll
            for (int mi = 0; mi < 2; mi++) {
                int r = wm + mi * 16 + lq;
                afr[mi][0] = f2tf32(As[r * G1_ASTR + kk + lr]);
                afr[mi][1] = f2tf32(As[(r + 8) * G1_ASTR + kk + lr]);
                afr[mi][2] = f2tf32(As[r * G1_ASTR + kk + lr + 4]);
                afr[mi][3] = f2tf32(As[(r + 8) * G1_ASTR + kk + lr + 4]);
            }
            uint32_t bfr[8][2];
#pragma unroll
            for (int ni = 0; ni < 8; ni++) {
                int c = wn + ni * 8 + lq;
                bfr[ni][0] = f2tf32(Bs[(kk + lr) * G1_BSTR + c]);
                bfr[ni][1] = f2tf32(Bs[(kk + lr + 4) * G1_BSTR + c]);
            }
#pragma unroll
            for (int mi = 0; mi < 2; mi++)
#pragma unroll
                for (int ni = 0; ni < 8; ni++)
                    mma_tf32(acc[mi][ni], afr[mi][0], afr[mi][1], afr[mi][2], afr[mi][3],
                             bfr[ni][0], bfr[ni][1]);
        }
        __syncthreads();
    }

#pragma unroll
    for (int mi = 0; mi < 2; mi++) {
#pragma unroll
        for (int ni = 0; ni < 8; ni++) {
            int r0 = m0 + wm + mi * 16 + lq;
            int c0 = n0 + wn + ni * 8 + 2 * lr;
            float bl = bias[c0];
            float bh = bias[c0 + 1];
            g_gates[(size_t)r0 * GDIM + c0]           = acc[mi][ni][0] + bl;
            g_gates[(size_t)r0 * GDIM + c0 + 1]       = acc[mi][ni][1] + bh;
            g_gates[(size_t)(r0 + 8) * GDIM + c0]     = acc[mi][ni][2] + bl;
            g_gates[(size_t)(r0 + 8) * GDIM + c0 + 1] = acc[mi][ni][3] + bh;
        }
    }
}

// ---------------- phase 2: persistent recurrent kernel ---------------------
// Round-1 lstm_step compute, with Wh slice resident in SMEM (as float) and a
// grid barrier between timesteps. CTA j owns hidden units [j*8, j*8+8).
// 4 warps; warp w handles batch rows [w*16, w*16+16), all 4 gates (g loop).
#define WS_STR 36
#define HS_STR 36
#define WS_WORDS (HDIM * WS_STR)        // 36864 floats
#define HS_WORDS (BATCH * HS_STR)       // 2304 floats
#define PSMEM_BYTES ((WS_WORDS + HS_WORDS) * 4)   // 156672 B

__device__ __forceinline__ void grid_barrier() {
    __syncthreads();
    if (threadIdx.x == 0) {
        __threadfence();
        unsigned gen = g_bar_gen;
        unsigned t = atomicAdd(&g_bar_count, 1u);
        if (t == NCTA - 1) {
            g_bar_count = 0;
            __threadfence();
            g_bar_gen = gen + 1;
        } else {
            while (g_bar_gen == gen) { }
            __threadfence();
        }
    }
    __syncthreads();
}

__global__ __launch_bounds__(NTHR, 1) void lstm_persist(const float* __restrict__ X,
                                                        const float* __restrict__ Wh,
                                                        float* __restrict__ ys) {
    extern __shared__ float dsm[];
    float* ws = dsm;                 // [1024][36] Wh slice (float)
    float* hs = dsm + WS_WORDS;      // [64][36]   h tile (single buffer)

    const int tid  = threadIdx.x;
    const int lane = tid & 31;
    const int w    = tid >> 5;       // warp 0..3 -> batch rows w*16..
    const int lq   = lane >> 2;
    const int lr   = lane & 3;
    const int j    = blockIdx.x;     // hidden slice

    // ---- preload Wh slice into SMEM once (round-1 indexing, float) ----
    {
        const int wk = tid >> 2;     // 0..31 (k row within 32-chunk)
        const int wg = tid & 3;      // gate 0..3
        for (int base = 0; base < HDIM; base += 32) {
            const float4* wsrc = (const float4*)(Wh + (size_t)(base + wk) * GDIM + wg * HDIM + j * 8);
            *(float4*)(ws + (base + wk) * WS_STR + wg * 8)     = wsrc[0];
            *(float4*)(ws + (base + wk) * WS_STR + wg * 8 + 4) = wsrc[1];
        }
    }
    __syncthreads();

    const int hr = tid >> 1;         // 0..63 (h tile row)
    const int hc = (tid & 1) * 16;   // 0 or 16

    for (int t = 0; t < T_STEPS; t++) {
        const int cur = t & 1;
        const int nxt = cur ^ 1;
        const float* hprev = g_h[cur];
        const float* cprev = g_c[cur];
        float* hnex = g_h[nxt];
        float* cnex = g_c[nxt];

        float acc[4][4];
#pragma unroll
        for (int g = 0; g < 4; g++)
#pragma unroll
            for (int q = 0; q < 4; q++) acc[g][q] = 0.0f;

        // preload tile 0 into registers (.cg: L1 may hold stale state data)
        float4 rv[4];
#pragma unroll
        for (int v = 0; v < 4; v++)
            rv[v] = ldcg4(hprev + (size_t)hr * HDIM + hc + v * 4);

        for (int it = 0; it < HDIM / 32; it++) {
            // stage current tile to smem
#pragma unroll
            for (int v = 0; v < 4; v++)
                *(float4*)(hs + hr * HS_STR + hc + v * 4) = rv[v];
            __syncthreads();

            // prefetch next tile (latency hidden behind compute)
            if (it + 1 < HDIM / 32) {
                int k1 = (it + 1) * 32;
#pragma unroll
                for (int v = 0; v < 4; v++)
                    rv[v] = ldcg4(hprev + (size_t)hr * HDIM + k1 + hc + v * 4);
            }

            const int k0 = it * 32;
#pragma unroll
            for (int kk = 0; kk < 32; kk += 8) {
                int r = w * 16 + lq;
                uint32_t a0 = f2tf32(hs[r * HS_STR + kk + lr]);
                uint32_t a1 = f2tf32(hs[(r + 8) * HS_STR + kk + lr]);
                uint32_t a2 = f2tf32(hs[r * HS_STR + kk + lr + 4]);
                uint32_t a3 = f2tf32(hs[(r + 8) * HS_STR + kk + lr + 4]);
#pragma unroll
                for (int g = 0; g < 4; g++) {
                    uint32_t b0 = f2tf32(ws[(k0 + kk + lr) * WS_STR + g * 8 + lq]);
                    uint32_t b1 = f2tf32(ws[(k0 + kk + lr + 4) * WS_STR + g * 8 + lq]);
                    mma_tf32(acc[g], a0, a1, a2, a3, b0, b1);
                }
            }
            __syncthreads();
        }

        // ---- elementwise LSTM cell (round-1 exact, .cg for mutable state) --
        const float* gx = g_gates + (size_t)t * BATCH * GDIM;

#pragma unroll
        for (int half = 0; half < 2; half++) {
            int r = w * 16 + lq + half * 8;
            bool m = (__ldcg(&g_eos[cur][r]) != 0);
#pragma unroll
            for (int cc = 0; cc < 2; cc++) {
                int ci   = half * 2 + cc;
                int hcol = j * 8 + 2 * lr + cc;
                float iv = acc[0][ci] + __ldg(gx + (size_t)r * GDIM + hcol);
                float fv = acc[1][ci] + __ldg(gx + (size_t)r * GDIM + HDIM + hcol);
                float gv = acc[2][ci] + __ldg(gx + (size_t)r * GDIM + 2 * HDIM + hcol);
                float ov = acc[3][ci] + __ldg(gx + (size_t)r * GDIM + 3 * HDIM + hcol);

                float cp  = __ldcg(cprev + (size_t)r * HDIM + hcol);
                float ncv = sigf(fv) * cp + sigf(iv) * tanhf(gv);
                float nhv = sigf(ov) * tanhf(ncv);

                ys[((size_t)t * BATCH + r) * HDIM + hcol] = nhv;   // unmasked
                cnex[(size_t)r * HDIM + hcol] = m ? cp : ncv;
                hnex[(size_t)r * HDIM + hcol] = m ? __ldcg(hprev + (size_t)r * HDIM + hcol) : nhv;
            }
        }

        if (blockIdx.x == 0 && tid < BATCH) {
            float xe = __ldg(X + ((size_t)t * BATCH + tid) * VDIM + 1);
            int eo = __ldcg(&g_eos[cur][tid]);
            g_eos[nxt][tid] = (eo != 0 || xe != 0.0f) ? 1 : 0;
        }

        __threadfence();
        grid_barrier();
    }
}

// ---------------- launch ---------------------------------------------------
extern "C" void kernel_launch(void* const* d_in, const int* in_sizes, int n_in,
                              void* d_out, int out_size) {
    const float* x  = (const float*)d_in[0];
    const float* Wi = (const float*)d_in[1];
    const float* Wh = (const float*)d_in[2];
    const float* b  = (const float*)d_in[3];
    const float* c0 = (const float*)d_in[4];
    const float* h0 = (const float*)d_in[5];
    const unsigned char* eos0 = (const unsigned char*)d_in[6];
    float* ys = (float*)d_out;

    static bool attr_done = false;
    if (!attr_done) {
        cudaFuncSetAttribute(lstm_persist,
                             cudaFuncAttributeMaxDynamicSharedMemorySize, PSMEM_BYTES);
        attr_done = true;
    }

    init_state<<<(BATCH * HDIM + 255) / 256, 256>>>(c0, h0, eos0);

    dim3 g1(GDIM / G1_BN, (T_STEPS * BATCH) / G1_BM);   // 32 x 64
    gemm1<<<g1, 256>>>(x, Wi, b);

    lstm_persist<<<NCTA, NTHR, PSMEM_BYTES>>>(x, Wh, ys);
}

// round 4
// speedup vs baseline: 1.8272x; 1.0224x over previous
#include <cuda_runtime.h>
#include <cstdint>

#define T_STEPS 128
#define BATCH   64
#define VDIM    2048
#define HDIM    1024
#define GDIM    4096   // 4*H

#define NCTA    128    // persistent CTAs (one per 8 hidden units)
#define NTHR    128    // 4 warps

// ---------------- scratch (static device globals; no allocation) ----------
__device__ float g_gates[(size_t)T_STEPS * BATCH * GDIM];  // 134 MB: x@Wi + b
__device__ float g_h[2][BATCH * HDIM];
__device__ float g_c[2][BATCH * HDIM];
__device__ int   g_eos[2][BATCH];
__device__ unsigned g_bar_count;
__device__ volatile unsigned g_bar_gen;

// ---------------- helpers ------------------------------------------------
__device__ __forceinline__ uint32_t f2tf32(float f) {
    uint32_t r;
    asm("cvt.rna.tf32.f32 %0, %1;" : "=r"(r) : "f"(f));
    return r;
}

__device__ __forceinline__ void st_tf32_4(uint32_t* d, float4 v) {
    uint4 u;
    u.x = f2tf32(v.x); u.y = f2tf32(v.y); u.z = f2tf32(v.z); u.w = f2tf32(v.w);
    *(uint4*)d = u;
}

__device__ __forceinline__ void mma_tf32(float c[4],
                                         uint32_t a0, uint32_t a1, uint32_t a2, uint32_t a3,
                                         uint32_t b0, uint32_t b1) {
    asm volatile(
        "mma.sync.aligned.m16n8k8.row.col.f32.tf32.tf32.f32 "
        "{%0,%1,%2,%3}, {%4,%5,%6,%7}, {%8,%9}, {%0,%1,%2,%3};\n"
        : "+f"(c[0]), "+f"(c[1]), "+f"(c[2]), "+f"(c[3])
        : "r"(a0), "r"(a1), "r"(a2), "r"(a3), "r"(b0), "r"(b1));
}

__device__ __forceinline__ float sigf(float x) {
    return 1.0f / (1.0f + expf(-x));
}

__device__ __forceinline__ float4 ldcg4(const float* p) {
    return __ldcg((const float4*)p);
}

// ---------------- init state ---------------------------------------------
__global__ void init_state(const float* __restrict__ c0,
                           const float* __restrict__ h0,
                           const unsigned char* __restrict__ eos0) {
    int i = blockIdx.x * blockDim.x + threadIdx.x;
    if (i < BATCH * HDIM) {
        g_c[0][i] = c0[i];
        g_h[0][i] = h0[i];
    }
    if (i < BATCH) g_eos[0][i] = eos0[i] ? 1 : 0;
    if (i == 0) { g_bar_count = 0; g_bar_gen = 0; }
}

// ---------------- phase 1: gates_x = X @ Wi + b ----------------------------
// Same layout as round 3, but: smem tiles pre-converted to tf32, double
// buffered, register prefetch, ONE __syncthreads per k-iter.
#define G1_BM 128
#define G1_BN 128
#define G1_BK 16
#define G1_ASTR 20
#define G1_BSTR 132

__global__ __launch_bounds__(256) void gemm1(const float* __restrict__ X,
                                             const float* __restrict__ Wi,
                                             const float* __restrict__ bias) {
    __shared__ uint32_t As[2][G1_BM * G1_ASTR];
    __shared__ uint32_t Bs[2][G1_BK * G1_BSTR];

    const int tid  = threadIdx.x;
    const int lane = tid & 31;
    const int wid  = tid >> 5;
    const int wm   = (wid >> 1) * 32;
    const int wn   = (wid & 1) * 64;
    const int lq   = lane >> 2;
    const int lr   = lane & 3;

    const int m0 = blockIdx.y * G1_BM;
    const int n0 = blockIdx.x * G1_BN;

    float acc[2][8][4];
#pragma unroll
    for (int mi = 0; mi < 2; mi++)
#pragma unroll
        for (int ni = 0; ni < 8; ni++)
#pragma unroll
            for (int q = 0; q < 4; q++) acc[mi][ni][q] = 0.0f;

    const int ar = tid >> 1;
    const int ac = (tid & 1) * 8;
    const int br = tid >> 4;
    const int bc = (tid & 15) * 8;

    const float* asrc = X  + (size_t)(m0 + ar) * VDIM + ac;
    const float* bsrc = Wi + (size_t)br * GDIM + n0 + bc;

    // prefetch k-tile 0 into registers
    float4 av0 = *(const float4*)(asrc);
    float4 av1 = *(const float4*)(asrc + 4);
    float4 bv0 = *(const float4*)(bsrc);
    float4 bv1 = *(const float4*)(bsrc + 4);

    const int NIT = VDIM / G1_BK;   // 128
    for (int it = 0; it < NIT; it++) {
        const int p = it & 1;
        // stage current tile (converted to tf32)
        st_tf32_4(&As[p][ar * G1_ASTR + ac],     av0);
        st_tf32_4(&As[p][ar * G1_ASTR + ac + 4], av1);
        st_tf32_4(&Bs[p][br * G1_BSTR + bc],     bv0);
        st_tf32_4(&Bs[p][br * G1_BSTR + bc + 4], bv1);
        __syncthreads();

        // prefetch next tile into registers
        if (it + 1 < NIT) {
            int k1 = (it + 1) * G1_BK;
            av0 = *(const float4*)(asrc + k1);
            av1 = *(const float4*)(asrc + k1 + 4);
            bv0 = *(const float4*)(bsrc + (size_t)k1 * GDIM);
            bv1 = *(const float4*)(bsrc + (size_t)k1 * GDIM + 4);
        }

        const uint32_t* as = As[p];
        const uint32_t* bs = Bs[p];
#pragma unroll
        for (int kk = 0; kk < G1_BK; kk += 8) {
            uint32_t afr[2][4];
#pragma unroll
            for (int mi = 0; mi < 2; mi++) {
                int r = wm + mi * 16 + lq;
                afr[mi][0] = as[r * G1_ASTR + kk + lr];
                afr[mi][1] = as[(r + 8) * G1_ASTR + kk + lr];
                afr[mi][2] = as[r * G1_ASTR + kk + lr + 4];
                afr[mi][3] = as[(r + 8) * G1_ASTR + kk + lr + 4];
            }
            uint32_t bfr[8][2];
#pragma unroll
            for (int ni = 0; ni < 8; ni++) {
                int c = wn + ni * 8 + lq;
                bfr[ni][0] = bs[(kk + lr) * G1_BSTR + c];
                bfr[ni][1] = bs[(kk + lr + 4) * G1_BSTR + c];
            }
#pragma unroll
            for (int mi = 0; mi < 2; mi++)
#pragma unroll
                for (int ni = 0; ni < 8; ni++)
                    mma_tf32(acc[mi][ni], afr[mi][0], afr[mi][1], afr[mi][2], afr[mi][3],
                             bfr[ni][0], bfr[ni][1]);
        }
        // no trailing sync: next iter writes the OTHER buffer; buffer p is
        // rewritten only at it+2, after sync(it+1) which every warp reaches
        // only after finishing compute(it).
    }

#pragma unroll
    for (int mi = 0; mi < 2; mi++) {
#pragma unroll
        for (int ni = 0; ni < 8; ni++) {
            int r0 = m0 + wm + mi * 16 + lq;
            int c0 = n0 + wn + ni * 8 + 2 * lr;
            float bl = bias[c0];
            float bh = bias[c0 + 1];
            g_gates[(size_t)r0 * GDIM + c0]           = acc[mi][ni][0] + bl;
            g_gates[(size_t)r0 * GDIM + c0 + 1]       = acc[mi][ni][1] + bh;
            g_gates[(size_t)(r0 + 8) * GDIM + c0]     = acc[mi][ni][2] + bl;
            g_gates[(size_t)(r0 + 8) * GDIM + c0 + 1] = acc[mi][ni][3] + bh;
        }
    }
}

// ---------------- phase 2: persistent recurrent kernel ---------------------
// Round-3 structure; ws and hs now hold pre-converted tf32, hs double
// buffered with a single sync per k-tile.
#define WS_STR 36
#define HS_STR 36
#define WS_WORDS (HDIM * WS_STR)            // 36864
#define HS_WORDS (2 * BATCH * HS_STR)       // 4608 (double buffer)
#define PSMEM_BYTES ((WS_WORDS + HS_WORDS) * 4)   // 165888 B

__device__ __forceinline__ void grid_barrier() {
    __syncthreads();
    if (threadIdx.x == 0) {
        __threadfence();
        unsigned gen = g_bar_gen;
        unsigned t = atomicAdd(&g_bar_count, 1u);
        if (t == NCTA - 1) {
            g_bar_count = 0;
            __threadfence();
            g_bar_gen = gen + 1;
        } else {
            while (g_bar_gen == gen) { }
            __threadfence();
        }
    }
    __syncthreads();
}

__global__ __launch_bounds__(NTHR, 1) void lstm_persist(const float* __restrict__ X,
                                                        const float* __restrict__ Wh,
                                                        float* __restrict__ ys) {
    extern __shared__ uint32_t dsm[];
    uint32_t* ws = dsm;                 // [1024][36] Wh slice (tf32)
    uint32_t* hs = dsm + WS_WORDS;      // [2][64][36] h tile (tf32, dbl buf)

    const int tid  = threadIdx.x;
    const int lane = tid & 31;
    const int w    = tid >> 5;       // warp 0..3 -> batch rows w*16..
    const int lq   = lane >> 2;
    const int lr   = lane & 3;
    const int j    = blockIdx.x;     // hidden slice

    // ---- preload Wh slice into SMEM once (converted to tf32) ----
    {
        const int wk = tid >> 2;     // 0..31
        const int wg = tid & 3;      // gate 0..3
        for (int base = 0; base < HDIM; base += 32) {
            const float4* wsrc = (const float4*)(Wh + (size_t)(base + wk) * GDIM + wg * HDIM + j * 8);
            st_tf32_4(ws + (base + wk) * WS_STR + wg * 8,     wsrc[0]);
            st_tf32_4(ws + (base + wk) * WS_STR + wg * 8 + 4, wsrc[1]);
        }
    }
    __syncthreads();

    const int hr = tid >> 1;         // 0..63 (h tile row)
    const int hc = (tid & 1) * 16;   // 0 or 16

    for (int t = 0; t < T_STEPS; t++) {
        const int cur = t & 1;
        const int nxt = cur ^ 1;
        const float* hprev = g_h[cur];
        const float* cprev = g_c[cur];
        float* hnex = g_h[nxt];
        float* cnex = g_c[nxt];

        float acc[4][4];
#pragma unroll
        for (int g = 0; g < 4; g++)
#pragma unroll
            for (int q = 0; q < 4; q++) acc[g][q] = 0.0f;

        // preload tile 0 into registers (.cg: L1 may hold stale state data)
        float4 rv[4];
#pragma unroll
        for (int v = 0; v < 4; v++)
            rv[v] = ldcg4(hprev + (size_t)hr * HDIM + hc + v * 4);

        for (int it = 0; it < HDIM / 32; it++) {
            uint32_t* hb = hs + (it & 1) * (BATCH * HS_STR);
            // stage current tile (converted)
#pragma unroll
            for (int v = 0; v < 4; v++)
                st_tf32_4(hb + hr * HS_STR + hc + v * 4, rv[v]);
            __syncthreads();

            // prefetch next tile
            if (it + 1 < HDIM / 32) {
                int k1 = (it + 1) * 32;
#pragma unroll
                for (int v = 0; v < 4; v++)
                    rv[v] = ldcg4(hprev + (size_t)hr * HDIM + k1 + hc + v * 4);
            }

            const int k0 = it * 32;
#pragma unroll
            for (int kk = 0; kk < 32; kk += 8) {
                int r = w * 16 + lq;
                uint32_t a0 = hb[r * HS_STR + kk + lr];
                uint32_t a1 = hb[(r + 8) * HS_STR + kk + lr];
                uint32_t a2 = hb[r * HS_STR + kk + lr + 4];
                uint32_t a3 = hb[(r + 8) * HS_STR + kk + lr + 4];
#pragma unroll
                for (int g = 0; g < 4; g++) {
                    uint32_t b0 = ws[(k0 + kk + lr) * WS_STR + g * 8 + lq];
                    uint32_t b1 = ws[(k0 + kk + lr + 4) * WS_STR + g * 8 + lq];
                    mma_tf32(acc[g], a0, a1, a2, a3, b0, b1);
                }
            }
            // single sync per tile: next iter writes the other buffer
        }

        // ---- elementwise LSTM cell (round-3 exact) ----
        const float* gx = g_gates + (size_t)t * BATCH * GDIM;

#pragma unroll
        for (int half = 0; half < 2; half++) {
            int r = w * 16 + lq + half * 8;
            bool m = (__ldcg(&g_eos[cur][r]) != 0);
#pragma unroll
            for (int cc = 0; cc < 2; cc++) {
                int ci   = half * 2 + cc;
                int hcol = j * 8 + 2 * lr + cc;
                float iv = acc[0][ci] + __ldg(gx + (size_t)r * GDIM + hcol);
                float fv = acc[1][ci] + __ldg(gx + (size_t)r * GDIM + HDIM + hcol);
                float gv = acc[2][ci] + __ldg(gx + (size_t)r * GDIM + 2 * HDIM + hcol);
                float ov = acc[3][ci] + __ldg(gx + (size_t)r * GDIM + 3 * HDIM + hcol);

                float cp  = __ldcg(cprev + (size_t)r * HDIM + hcol);
                float ncv = sigf(fv) * cp + sigf(iv) * tanhf(gv);
                float nhv = sigf(ov) * tanhf(ncv);

                ys[((size_t)t * BATCH + r) * HDIM + hcol] = nhv;   // unmasked
                cnex[(size_t)r * HDIM + hcol] = m ? cp : ncv;
                hnex[(size_t)r * HDIM + hcol] = m ? __ldcg(hprev + (size_t)r * HDIM + hcol) : nhv;
            }
        }

        if (blockIdx.x == 0 && tid < BATCH) {
            float xe = __ldg(X + ((size_t)t * BATCH + tid) * VDIM + 1);
            int eo = __ldcg(&g_eos[cur][tid]);
            g_eos[nxt][tid] = (eo != 0 || xe != 0.0f) ? 1 : 0;
        }

        __threadfence();
        grid_barrier();
    }
}

// ---------------- launch ---------------------------------------------------
extern "C" void kernel_launch(void* const* d_in, const int* in_sizes, int n_in,
                              void* d_out, int out_size) {
    const float* x  = (const float*)d_in[0];
    const float* Wi = (const float*)d_in[1];
    const float* Wh = (const float*)d_in[2];
    const float* b  = (const float*)d_in[3];
    const float* c0 = (const float*)d_in[4];
    const float* h0 = (const float*)d_in[5];
    const unsigned char* eos0 = (const unsigned char*)d_in[6];
    float* ys = (float*)d_out;

    static bool attr_done = false;
    if (!attr_done) {
        cudaFuncSetAttribute(lstm_persist,
                             cudaFuncAttributeMaxDynamicSharedMemorySize, PSMEM_BYTES);
        attr_done = true;
    }

    init_state<<<(BATCH * HDIM + 255) / 256, 256>>>(c0, h0, eos0);

    dim3 g1(GDIM / G1_BN, (T_STEPS * BATCH) / G1_BM);   // 32 x 64
    gemm1<<<g1, 256>>>(x, Wi, b);

    lstm_persist<<<NCTA, NTHR, PSMEM_BYTES>>>(x, Wh, ys);
}